// round 16
// baseline (speedup 1.0000x reference)
#include <cuda_runtime.h>
#include <cuda_fp16.h>
#include <math.h>
#include <stdint.h>

// Problem dims (fixed)
#define BB 4
#define SS 2048
#define MD 1024
#define HD 1024
#define NT 8192   // BB*SS

// GEMM tiling: CTA 128x128, 8 warps (2x4) of 64x32, K-chunk 64, 1-pass fp16
// occupancy 2 CTAs/SM
#define KC 64
#define STG    32768          // A(16K) + B(16K)
#define NS     3              // pipeline stages
#define SMEMSZ (NS * STG)     // 96 KB -> 2 CTAs/SM

#define SWZ(o) ((o) ^ (((o) >> 3) & 0x70))

// ---------------------------------------------------------------------------
// Scratch (__device__ globals; allocation-free rule)
// ---------------------------------------------------------------------------
__device__ __align__(256) __half g_Xq_hi[(size_t)NT * MD];
__device__ __align__(256) __half g_Xk_hi[(size_t)NT * MD];
__device__ __align__(256) __half g_Xv_hi[(size_t)NT * MD];
__device__ __align__(256) __half g_Wq_hi[(size_t)HD * MD];
__device__ __align__(256) __half g_Wk_hi[(size_t)HD * MD];
__device__ __align__(256) __half g_Wv_hi[(size_t)HD * MD];
__device__ __align__(256) __half g_QH_hi[(size_t)NT * HD];
__device__ __align__(256) __half g_KH_hi[(size_t)NT * HD];
__device__ __align__(256) __half g_VT_hi[(size_t)BB * HD * SS];
__device__ __align__(256) __half g_SC[(size_t)BB * SS * SS];     // fp16 scores
__device__ __align__(256) __half g_P_hi[(size_t)BB * SS * SS];

// ---------------------------------------------------------------------------
__device__ __forceinline__ uint32_t smem_u32(const void* p) {
    uint32_t a;
    asm("{ .reg .u64 t; cvta.to.shared.u64 t, %1; cvt.u32.u64 %0, t; }"
        : "=r"(a) : "l"(p));
    return a;
}
// .ca keeps the line in L1: cross-CTA tile reuse (2 CTAs/SM) can hit L1.
#define CP16(dst, src) asm volatile("cp.async.ca.shared.global [%0], [%1], 16;" :: "r"(dst), "l"(src))
#define CP_COMMIT()    asm volatile("cp.async.commit_group;" ::: "memory")
#define CP_WAIT1()     asm volatile("cp.async.wait_group 1;" ::: "memory")

__device__ __forceinline__ void ldsm4(uint32_t r[4], uint32_t a) {
    asm volatile("ldmatrix.sync.aligned.m8n8.x4.shared.b16 {%0,%1,%2,%3}, [%4];"
                 : "=r"(r[0]), "=r"(r[1]), "=r"(r[2]), "=r"(r[3]) : "r"(a));
}
__device__ __forceinline__ void mma_f32(float d[4], const uint32_t a[4],
                                        uint32_t b0, uint32_t b1) {
    asm volatile(
        "mma.sync.aligned.m16n8k16.row.col.f32.f16.f16.f32 "
        "{%0,%1,%2,%3}, {%4,%5,%6,%7}, {%8,%9}, {%0,%1,%2,%3};"
        : "+f"(d[0]), "+f"(d[1]), "+f"(d[2]), "+f"(d[3])
        : "r"(a[0]), "r"(a[1]), "r"(a[2]), "r"(a[3]), "r"(b0), "r"(b1));
}

__device__ __forceinline__ uint32_t pack_h2(__half a, __half b) {
    union { __half2 v; uint32_t u; } t;
    t.v.x = a; t.v.y = b;
    return t.u;
}

// ---------------------------------------------------------------------------
// GEMM mainloop (1-pass fp16 NT), CTA tile 128x128, warp tile 64x32.
// ---------------------------------------------------------------------------
struct GemmCtx {
    const char* gA;
    const char* gB;
    size_t ldaB, ldbB;
};

__device__ __forceinline__ void gemm_mainloop(
    const GemmCtx& cx, uint32_t sb, int tid, int lane, int wm, int wn,
    int nkt, float acc[4][4][4])
{
    auto load_chunk = [&](int c, int buf) {
        const uint32_t st = sb + buf * STG;
        const size_t cb = (size_t)c * 128;
#pragma unroll
        for (int i = 0; i < 4; ++i) {          // A: 128 rows x 128B
            const int idx = tid + i * 256;
            const int row = idx >> 3, seg = (idx & 7) * 16;
            CP16(st + SWZ(row * 128 + seg), cx.gA + (size_t)row * cx.ldaB + cb + seg);
        }
#pragma unroll
        for (int i = 0; i < 4; ++i) {          // B: 128 rows x 128B
            const int idx = tid + i * 256;
            const int row = idx >> 3, seg = (idx & 7) * 16;
            CP16(st + 16384 + SWZ(row * 128 + seg), cx.gB + (size_t)row * cx.ldbB + cb + seg);
        }
        CP_COMMIT();
    };

    const int lrow = lane & 15;
    const int lcb0 = (lane >> 4) * 16;
    const int arow = wm * 64 + lrow;
    const int brow = wn * 32 + lrow;

#pragma unroll
    for (int i = 0; i < NS - 1; ++i)
        if (i < nkt) load_chunk(i, i);
        else         CP_COMMIT();

    for (int c = 0; c < nkt; ++c) {
        CP_WAIT1();
        __syncthreads();
        if (c + NS - 1 < nkt) load_chunk(c + NS - 1, (c + NS - 1) % NS);
        else                  CP_COMMIT();   // keep wait-group count aligned

        const uint32_t st = sb + (c % NS) * STG;
#pragma unroll
        for (int kk = 0; kk < 4; ++kk) {
            const int cb = kk * 32 + lcb0;
            uint32_t a[4][4], bh[2][4];
#pragma unroll
            for (int mi = 0; mi < 4; ++mi)
                ldsm4(a[mi], st + SWZ((arow + mi * 16) * 128 + cb));
#pragma unroll
            for (int nj = 0; nj < 2; ++nj)
                ldsm4(bh[nj], st + 16384 + SWZ((brow + nj * 16) * 128 + cb));
#pragma unroll
            for (int mi = 0; mi < 4; ++mi)
#pragma unroll
                for (int nj = 0; nj < 2; ++nj) {
                    mma_f32(acc[mi][nj * 2 + 0], a[mi], bh[nj][0], bh[nj][2]);
                    mma_f32(acc[mi][nj * 2 + 1], a[mi], bh[nj][1], bh[nj][3]);
                }
        }
    }
}

// ---------------------------------------------------------------------------
// Q/K projections: grid.z in {0,1} selects q/k. Row-major fp16 out + bias.
// ---------------------------------------------------------------------------
__global__ void __launch_bounds__(256, 2)
gemm_proj_qk(const __half* __restrict__ A0, const __half* __restrict__ A1,
             const __half* __restrict__ B0, const __half* __restrict__ B1,
             const float* __restrict__ b0p, const float* __restrict__ b1p,
             __half* __restrict__ C0, __half* __restrict__ C1)
{
    const int bm = blockIdx.y, bn = blockIdx.x, t = blockIdx.z;
    const __half* A   = (t == 0) ? A0 : A1;
    const __half* B   = (t == 0) ? B0 : B1;
    const float* bias = (t == 0) ? b0p : b1p;
    __half* Ch        = (t == 0) ? C0 : C1;

    extern __shared__ char smem[];
    const uint32_t sb = smem_u32(smem);
    const int tid = threadIdx.x, lane = tid & 31, wid = tid >> 5;
    const int wm = wid >> 2, wn = wid & 3;

    GemmCtx cx;
    cx.gA = (const char*)(A + (size_t)(bm * 128) * MD);
    cx.gB = (const char*)(B + (size_t)(bn * 128) * MD);
    cx.ldaB = (size_t)MD * 2;
    cx.ldbB = (size_t)MD * 2;

    float acc[4][4][4];
#pragma unroll
    for (int mi = 0; mi < 4; ++mi)
#pragma unroll
        for (int nf = 0; nf < 4; ++nf)
#pragma unroll
            for (int r = 0; r < 4; ++r) acc[mi][nf][r] = 0.f;

    gemm_mainloop(cx, sb, tid, lane, wm, wn, MD / KC, acc);

    const int lr = lane >> 2;
    const int lc = (lane & 3) * 2;
#pragma unroll
    for (int mi = 0; mi < 4; ++mi) {
        const int row0 = bm * 128 + wm * 64 + mi * 16 + lr;
#pragma unroll
        for (int nf = 0; nf < 4; ++nf) {
            const int col = bn * 128 + wn * 32 + nf * 8 + lc;
            float* d = acc[mi][nf];
            const float bb0 = bias[col], bb1 = bias[col + 1];
            *(uint32_t*)(Ch + (size_t)row0 * HD + col) =
                pack_h2(__float2half_rn(d[0] + bb0), __float2half_rn(d[1] + bb1));
            *(uint32_t*)(Ch + (size_t)(row0 + 8) * HD + col) =
                pack_h2(__float2half_rn(d[2] + bb0), __float2half_rn(d[3] + bb1));
        }
    }
}

// ---------------------------------------------------------------------------
// Merged launch, grid (16, 24, 4): z = batch.
//   y < 16 -> scores tile (bm=y, bn=x, causal skip bn>bm), fp16 out * alpha
//   y >= 16 -> V projection CTA idx = z*128 + (y-16)*16 + x, writes VT.
// ---------------------------------------------------------------------------
__global__ void __launch_bounds__(256, 2)
gemm_sc_vp(const __half* __restrict__ QH, const __half* __restrict__ KH,
           __half* __restrict__ SCh, float alpha,
           const __half* __restrict__ Xv, const __half* __restrict__ Wv,
           const float* __restrict__ bv, __half* __restrict__ VT)
{
    const int z = blockIdx.z;
    extern __shared__ char smem[];
    const uint32_t sb = smem_u32(smem);
    const int tid = threadIdx.x, lane = tid & 31, wid = tid >> 5;
    const int wm = wid >> 2, wn = wid & 3;
    const int lr = lane >> 2;
    const int lc = (lane & 3) * 2;

    if (blockIdx.y < 16) {
        const int bm = blockIdx.y, bn = blockIdx.x;
        if (bn > bm) return;

        GemmCtx cx;
        cx.gA = (const char*)(QH + (size_t)z * SS * HD + (size_t)(bm * 128) * HD);
        cx.gB = (const char*)(KH + (size_t)z * SS * HD + (size_t)(bn * 128) * HD);
        cx.ldaB = (size_t)HD * 2;
        cx.ldbB = (size_t)HD * 2;

        float acc[4][4][4];
#pragma unroll
        for (int mi = 0; mi < 4; ++mi)
#pragma unroll
            for (int nf = 0; nf < 4; ++nf)
#pragma unroll
                for (int r = 0; r < 4; ++r) acc[mi][nf][r] = 0.f;

        gemm_mainloop(cx, sb, tid, lane, wm, wn, HD / KC, acc);

        __half* cp = SCh + (size_t)z * SS * SS;
#pragma unroll
        for (int mi = 0; mi < 4; ++mi) {
            const int row0 = bm * 128 + wm * 64 + mi * 16 + lr;
#pragma unroll
            for (int nf = 0; nf < 4; ++nf) {
                const int col = bn * 128 + wn * 32 + nf * 8 + lc;
                float* d = acc[mi][nf];
                *(uint32_t*)(cp + (size_t)row0 * SS + col) =
                    pack_h2(__float2half_rn(d[0] * alpha), __float2half_rn(d[1] * alpha));
                *(uint32_t*)(cp + (size_t)(row0 + 8) * SS + col) =
                    pack_h2(__float2half_rn(d[2] * alpha), __float2half_rn(d[3] * alpha));
            }
        }
    } else {
        const int idx = z * 128 + (blockIdx.y - 16) * 16 + blockIdx.x;  // 0..511
        const int bn = idx & 7;     // HD/128 = 8
        const int bm = idx >> 3;    // NT/128 = 64

        GemmCtx cx;
        cx.gA = (const char*)(Xv + (size_t)(bm * 128) * MD);
        cx.gB = (const char*)(Wv + (size_t)(bn * 128) * MD);
        cx.ldaB = (size_t)MD * 2;
        cx.ldbB = (size_t)MD * 2;

        float acc[4][4][4];
#pragma unroll
        for (int mi = 0; mi < 4; ++mi)
#pragma unroll
            for (int nf = 0; nf < 4; ++nf)
#pragma unroll
                for (int r = 0; r < 4; ++r) acc[mi][nf][r] = 0.f;

        gemm_mainloop(cx, sb, tid, lane, wm, wn, MD / KC, acc);

        // transpose tile through smem -> VT[b][h][s] coalesced
        __syncthreads();   // pipeline smem no longer in use
        constexpr int TP = 136;                 // padded row (halfs)
        __half* ts = (__half*)smem;             // [128][TP] = 34816 B
#pragma unroll
        for (int mi = 0; mi < 4; ++mi) {
            const int sl0 = wm * 64 + mi * 16 + lr;
#pragma unroll
            for (int nf = 0; nf < 4; ++nf) {
                const int hl = wn * 32 + nf * 8 + lc;
                float* d = acc[mi][nf];
                const float bb0 = bv[bn * 128 + hl], bb1 = bv[bn * 128 + hl + 1];
                ts[(hl + 0) * TP + sl0]     = __float2half_rn(d[0] + bb0);
                ts[(hl + 1) * TP + sl0]     = __float2half_rn(d[1] + bb1);
                ts[(hl + 0) * TP + sl0 + 8] = __float2half_rn(d[2] + bb0);
                ts[(hl + 1) * TP + sl0 + 8] = __float2half_rn(d[3] + bb1);
            }
        }
        __syncthreads();
        const int grow = bm * 128;
        const int b    = grow >> 11;            // SS = 2048
        const int s0   = grow & 2047;
        __half* dst = VT + (size_t)b * HD * SS + s0;
#pragma unroll
        for (int it = 0; it < 8; ++it) {        // 2048 uint4 units
            const int i2 = tid + it * 256;
            const int hl = i2 >> 4, seg = (i2 & 15) * 8;
            *(uint4*)(dst + (size_t)(bn * 128 + hl) * SS + seg) =
                *(const uint4*)&ts[hl * TP + seg];
        }
    }
}

// ---------------------------------------------------------------------------
// PV GEMM: OUT = P @ VT^T, k-chunks limited by causality, longest-first.
// ---------------------------------------------------------------------------
__global__ void __launch_bounds__(256, 2)
gemm_pv(const __half* __restrict__ A, const __half* __restrict__ B,
        float* __restrict__ Cf)
{
    const int bm = (int)gridDim.y - 1 - blockIdx.y;   // longest first
    const int bn = blockIdx.x, bz = blockIdx.z;
    const int nkt = (bm + 1) * 2;

    extern __shared__ char smem[];
    const uint32_t sb = smem_u32(smem);
    const int tid = threadIdx.x, lane = tid & 31, wid = tid >> 5;
    const int wm = wid >> 2, wn = wid & 3;

    GemmCtx cx;
    cx.gA = (const char*)(A + (size_t)bz * SS * SS + (size_t)(bm * 128) * SS);
    cx.gB = (const char*)(B + (size_t)bz * HD * SS + (size_t)(bn * 128) * SS);
    cx.ldaB = (size_t)SS * 2;
    cx.ldbB = (size_t)SS * 2;

    float acc[4][4][4];
#pragma unroll
    for (int mi = 0; mi < 4; ++mi)
#pragma unroll
        for (int nf = 0; nf < 4; ++nf)
#pragma unroll
            for (int r = 0; r < 4; ++r) acc[mi][nf][r] = 0.f;

    gemm_mainloop(cx, sb, tid, lane, wm, wn, nkt, acc);

    const int lr = lane >> 2;
    const int lc = (lane & 3) * 2;
    float* cp = Cf + (size_t)bz * SS * HD;
#pragma unroll
    for (int mi = 0; mi < 4; ++mi) {
        const int row0 = bm * 128 + wm * 64 + mi * 16 + lr;
#pragma unroll
        for (int nf = 0; nf < 4; ++nf) {
            const int col = bn * 128 + wn * 32 + nf * 8 + lc;
            float* d = acc[mi][nf];
            float2 o0 = { d[0], d[1] };
            float2 o1 = { d[2], d[3] };
            *(float2*)(cp + (size_t)row0 * HD + col) = o0;
            *(float2*)(cp + (size_t)(row0 + 8) * HD + col) = o1;
        }
    }
}

// ---------------------------------------------------------------------------
// Fused convert: grid (2048, 4). y<3 -> X tensors (2048 blocks each);
// y==3 -> the 3 W tensors packed into x<768 (256 blocks each).
// ---------------------------------------------------------------------------
__global__ void __launch_bounds__(256)
convert_hi6(const float* __restrict__ s0, const float* __restrict__ s1,
            const float* __restrict__ s2, const float* __restrict__ s3,
            const float* __restrict__ s4, const float* __restrict__ s5,
            __half* __restrict__ h0, __half* __restrict__ h1,
            __half* __restrict__ h2, __half* __restrict__ h3,
            __half* __restrict__ h4, __half* __restrict__ h5,
            size_t nX4, size_t nW4)
{
    int t;
    size_t i0;
    if (blockIdx.y < 3) {
        t = blockIdx.y;
        i0 = ((size_t)blockIdx.x * blockDim.x + threadIdx.x) * 4;
        if (i0 >= nX4) return;
    } else {
        const unsigned xb = blockIdx.x;
        if (xb >= 768) return;
        t = 3 + (int)(xb >> 8);
        i0 = ((size_t)(xb & 255) * blockDim.x + threadIdx.x) * 4;
        if (i0 >= nW4) return;
    }
    const float* src = (t == 0) ? s0 : (t == 1) ? s1 : (t == 2) ? s2
                     : (t == 3) ? s3 : (t == 4) ? s4 : s5;
    __half* hi = (t == 0) ? h0 : (t == 1) ? h1 : (t == 2) ? h2
               : (t == 3) ? h3 : (t == 4) ? h4 : h5;
    float4 x[4];
#pragma unroll
    for (int u = 0; u < 4; ++u) x[u] = ((const float4*)src)[i0 + u];
#pragma unroll
    for (int u = 0; u < 4; ++u) {
        union { __half h[4]; uint2 v; } H;
        H.h[0] = __float2half_rn(x[u].x);
        H.h[1] = __float2half_rn(x[u].y);
        H.h[2] = __float2half_rn(x[u].z);
        H.h[3] = __float2half_rn(x[u].w);
        ((uint2*)hi)[i0 + u] = H.v;
    }
}

// ---------------------------------------------------------------------------
// Masked causal softmax: SC fp16 -> P fp16, zero-filled to 128-boundary.
// ---------------------------------------------------------------------------
__global__ void __launch_bounds__(256)
softmax_rows(const int* __restrict__ mask, const __half* __restrict__ SC,
             __half* __restrict__ Phi)
{
    const int b = blockIdx.y;
    const int i = blockIdx.x;
    const size_t rowoff = ((size_t)b * SS + i) * SS;
    const __half* row = SC + rowoff;
    const int* mrow = mask + (size_t)b * SS;
    const int tid = threadIdx.x;
    const int nvalid = i + 1;
    const int nfill = ((i >> 7) + 1) << 7;
    const int j0 = tid * 8;

    float vals[8];
    float vmax = -INFINITY;
    if (j0 + 7 < nvalid) {
        uint4 r8 = *(const uint4*)(row + j0);   // 8 halfs
        const __half2* hp = (const __half2*)&r8;
        float2 f0 = __half22float2(hp[0]);
        float2 f1 = __half22float2(hp[1]);
        float2 f2 = __half22float2(hp[2]);
        float2 f3 = __half22float2(hp[3]);
        int4 m0 = *(const int4*)(mrow + j0);
        int4 m1 = *(const int4*)(mrow + j0 + 4);
        vals[0] = m0.x ? f0.x : -1e9f; vals[1] = m0.y ? f0.y : -1e9f;
        vals[2] = m0.z ? f1.x : -1e9f; vals[3] = m0.w ? f1.y : -1e9f;
        vals[4] = m1.x ? f2.x : -1e9f; vals[5] = m1.y ? f2.y : -1e9f;
        vals[6] = m1.z ? f3.x : -1e9f; vals[7] = m1.w ? f3.y : -1e9f;
#pragma unroll
        for (int t = 0; t < 8; ++t) vmax = fmaxf(vmax, vals[t]);
    } else {
#pragma unroll
        for (int t = 0; t < 8; ++t) {
            int j = j0 + t;
            float s = -INFINITY;
            if (j < nvalid) {
                s = __half2float(row[j]);
                if (mrow[j] == 0) s = -1e9f;
            }
            vals[t] = s;
            vmax = fmaxf(vmax, s);
        }
    }

    __shared__ float red[8];
#pragma unroll
    for (int o = 16; o; o >>= 1) vmax = fmaxf(vmax, __shfl_xor_sync(~0u, vmax, o));
    if ((tid & 31) == 0) red[tid >> 5] = vmax;
    __syncthreads();
    if (tid < 32) {
        float x = (tid < 8) ? red[tid] : -INFINITY;
#pragma unroll
        for (int o = 4; o; o >>= 1) x = fmaxf(x, __shfl_xor_sync(~0u, x, o));
        if (tid == 0) red[0] = x;
    }
    __syncthreads();
    vmax = red[0];
    __syncthreads();

    float lsum = 0.f;
#pragma unroll
    for (int t = 0; t < 8; ++t) {
        float e = __expf(vals[t] - vmax);
        vals[t] = e;
        lsum += e;
    }
#pragma unroll
    for (int o = 16; o; o >>= 1) lsum += __shfl_xor_sync(~0u, lsum, o);
    if ((tid & 31) == 0) red[tid >> 5] = lsum;
    __syncthreads();
    if (tid < 32) {
        float x = (tid < 8) ? red[tid] : 0.f;
#pragma unroll
        for (int o = 4; o; o >>= 1) x += __shfl_xor_sync(~0u, x, o);
        if (tid == 0) red[0] = x;
    }
    __syncthreads();
    const float rinv = 1.0f / red[0];

    if (j0 < nfill) {
        union { __half h[8]; uint4 u; } P;
#pragma unroll
        for (int t = 0; t < 8; ++t)
            P.h[t] = __float2half_rn(vals[t] * rinv);   // 0 for j > i
        *(uint4*)(Phi + rowoff + j0) = P.u;
    }
}

// ---------------------------------------------------------------------------
extern "C" void kernel_launch(void* const* d_in, const int* in_sizes, int n_in,
                              void* d_out, int out_size)
{
    (void)in_sizes; (void)n_in; (void)out_size;

    const float* q    = (const float*)d_in[0];
    const float* k    = (const float*)d_in[1];
    const float* v    = (const float*)d_in[2];
    const int*   mask = (const int*)  d_in[3];
    const float* Wq   = (const float*)d_in[4];
    const float* bq   = (const float*)d_in[5];
    const float* Wk   = (const float*)d_in[6];
    const float* bk   = (const float*)d_in[7];
    const float* Wv   = (const float*)d_in[8];
    const float* bv   = (const float*)d_in[9];
    float* out = (float*)d_out;

    static bool init = false;
    static __half *Xqh, *Xkh, *Xvh, *Wqh, *Wkh, *Wvh;
    static __half *QHh, *KHh, *VTh, *Ph, *SC;
    if (!init) {
        void* p;
        cudaGetSymbolAddress(&p, g_Xq_hi); Xqh = (__half*)p;
        cudaGetSymbolAddress(&p, g_Xk_hi); Xkh = (__half*)p;
        cudaGetSymbolAddress(&p, g_Xv_hi); Xvh = (__half*)p;
        cudaGetSymbolAddress(&p, g_Wq_hi); Wqh = (__half*)p;
        cudaGetSymbolAddress(&p, g_Wk_hi); Wkh = (__half*)p;
        cudaGetSymbolAddress(&p, g_Wv_hi); Wvh = (__half*)p;
        cudaGetSymbolAddress(&p, g_QH_hi); QHh = (__half*)p;
        cudaGetSymbolAddress(&p, g_KH_hi); KHh = (__half*)p;
        cudaGetSymbolAddress(&p, g_VT_hi); VTh = (__half*)p;
        cudaGetSymbolAddress(&p, g_P_hi);  Ph  = (__half*)p;
        cudaGetSymbolAddress(&p, g_SC);    SC  = (__half*)p;
        cudaFuncSetAttribute((const void*)gemm_proj_qk, cudaFuncAttributeMaxDynamicSharedMemorySize, SMEMSZ);
        cudaFuncSetAttribute((const void*)gemm_sc_vp,   cudaFuncAttributeMaxDynamicSharedMemorySize, SMEMSZ);
        cudaFuncSetAttribute((const void*)gemm_pv,      cudaFuncAttributeMaxDynamicSharedMemorySize, SMEMSZ);
        init = true;
    }

    // 1) Convert all 6 inputs to fp16 (tight grid: W packed into y==3)
    const size_t nX4 = (size_t)NT * MD / 4;
    const size_t nW4 = (size_t)HD * MD / 4;
    convert_hi6<<<dim3(2048, 4), 256>>>(
        q, k, v, Wq, Wk, Wv, Xqh, Xkh, Xvh, Wqh, Wkh, Wvh, nX4, nW4);

    // 2) Q/K projections in one launch
    dim3 gqk(HD / 128, NT / 128, 2);
    gemm_proj_qk<<<gqk, 256, SMEMSZ>>>(Xqh, Xkh, Wqh, Wkh, bq, bk, QHh, KHh);

    // 3) Merged: scores (y<16, causal skip) + V projection (y>=16)
    dim3 gsv(16, 24, 4);
    gemm_sc_vp<<<gsv, 256, SMEMSZ>>>(QHh, KHh, SC, 1.0f / 32.0f,
                                     Xvh, Wvh, bv, VTh);

    // 4) Softmax (fp16 scores) -> P fp16
    softmax_rows<<<dim3(SS, BB), 256>>>(mask, SC, Ph);

    // 5) OUT = P @ VT^T (longest-first CTA order)
    dim3 go(HD / 128, SS / 128, BB);
    gemm_pv<<<go, 256, SMEMSZ>>>(Ph, VTh, out);
}

// round 17
// speedup vs baseline: 1.0844x; 1.0844x over previous
#include <cuda_runtime.h>
#include <cuda_fp16.h>
#include <math.h>
#include <stdint.h>

// Problem dims (fixed)
#define BB 4
#define SS 2048
#define MD 1024
#define HD 1024
#define NT 8192   // BB*SS

// GEMM tiling: CTA 128x128, 8 warps (2x4) of 64x32, K-chunk 64, 1-pass fp16
// occupancy 2 CTAs/SM
#define KC 64
#define STG    32768          // A(16K) + B(16K)
#define NS     3              // pipeline stages
#define SMEMSZ (NS * STG)     // 96 KB -> 2 CTAs/SM

#define SWZ(o) ((o) ^ (((o) >> 3) & 0x70))

// ---------------------------------------------------------------------------
// Scratch (__device__ globals; allocation-free rule)
// ---------------------------------------------------------------------------
__device__ __align__(256) __half g_Xq_hi[(size_t)NT * MD];
__device__ __align__(256) __half g_Xk_hi[(size_t)NT * MD];
__device__ __align__(256) __half g_Xv_hi[(size_t)NT * MD];
__device__ __align__(256) __half g_Wq_hi[(size_t)HD * MD];
__device__ __align__(256) __half g_Wk_hi[(size_t)HD * MD];
__device__ __align__(256) __half g_Wv_hi[(size_t)HD * MD];
__device__ __align__(256) __half g_QH_hi[(size_t)NT * HD];
__device__ __align__(256) __half g_KH_hi[(size_t)NT * HD];
__device__ __align__(256) __half g_VT_hi[(size_t)BB * HD * SS];
__device__ __align__(256) __half g_SC[(size_t)BB * SS * SS];     // fp16 scores
__device__ __align__(256) __half g_P_hi[(size_t)BB * SS * SS];

// ---------------------------------------------------------------------------
__device__ __forceinline__ uint32_t smem_u32(const void* p) {
    uint32_t a;
    asm("{ .reg .u64 t; cvta.to.shared.u64 t, %1; cvt.u32.u64 %0, t; }"
        : "=r"(a) : "l"(p));
    return a;
}
// .cg: L2-only fills. (.ca measured 25us SLOWER in R16 — L1 thrash.)
#define CP16(dst, src) asm volatile("cp.async.cg.shared.global [%0], [%1], 16;" :: "r"(dst), "l"(src))
#define CP_COMMIT()    asm volatile("cp.async.commit_group;" ::: "memory")
#define CP_WAIT1()     asm volatile("cp.async.wait_group 1;" ::: "memory")

__device__ __forceinline__ void ldsm4(uint32_t r[4], uint32_t a) {
    asm volatile("ldmatrix.sync.aligned.m8n8.x4.shared.b16 {%0,%1,%2,%3}, [%4];"
                 : "=r"(r[0]), "=r"(r[1]), "=r"(r[2]), "=r"(r[3]) : "r"(a));
}
__device__ __forceinline__ void mma_f32(float d[4], const uint32_t a[4],
                                        uint32_t b0, uint32_t b1) {
    asm volatile(
        "mma.sync.aligned.m16n8k16.row.col.f32.f16.f16.f32 "
        "{%0,%1,%2,%3}, {%4,%5,%6,%7}, {%8,%9}, {%0,%1,%2,%3};"
        : "+f"(d[0]), "+f"(d[1]), "+f"(d[2]), "+f"(d[3])
        : "r"(a[0]), "r"(a[1]), "r"(a[2]), "r"(a[3]), "r"(b0), "r"(b1));
}

__device__ __forceinline__ uint32_t pack_h2(__half a, __half b) {
    union { __half2 v; uint32_t u; } t;
    t.v.x = a; t.v.y = b;
    return t.u;
}

// ---------------------------------------------------------------------------
// GEMM mainloop (1-pass fp16 NT), CTA tile 128x128, warp tile 64x32.
// ---------------------------------------------------------------------------
struct GemmCtx {
    const char* gA;
    const char* gB;
    size_t ldaB, ldbB;
};

__device__ __forceinline__ void gemm_mainloop(
    const GemmCtx& cx, uint32_t sb, int tid, int lane, int wm, int wn,
    int nkt, float acc[4][4][4])
{
    auto load_chunk = [&](int c, int buf) {
        const uint32_t st = sb + buf * STG;
        const size_t cb = (size_t)c * 128;
#pragma unroll
        for (int i = 0; i < 4; ++i) {          // A: 128 rows x 128B
            const int idx = tid + i * 256;
            const int row = idx >> 3, seg = (idx & 7) * 16;
            CP16(st + SWZ(row * 128 + seg), cx.gA + (size_t)row * cx.ldaB + cb + seg);
        }
#pragma unroll
        for (int i = 0; i < 4; ++i) {          // B: 128 rows x 128B
            const int idx = tid + i * 256;
            const int row = idx >> 3, seg = (idx & 7) * 16;
            CP16(st + 16384 + SWZ(row * 128 + seg), cx.gB + (size_t)row * cx.ldbB + cb + seg);
        }
        CP_COMMIT();
    };

    const int lrow = lane & 15;
    const int lcb0 = (lane >> 4) * 16;
    const int arow = wm * 64 + lrow;
    const int brow = wn * 32 + lrow;

#pragma unroll
    for (int i = 0; i < NS - 1; ++i)
        if (i < nkt) load_chunk(i, i);
        else         CP_COMMIT();

    for (int c = 0; c < nkt; ++c) {
        CP_WAIT1();
        __syncthreads();
        if (c + NS - 1 < nkt) load_chunk(c + NS - 1, (c + NS - 1) % NS);
        else                  CP_COMMIT();   // keep wait-group count aligned

        const uint32_t st = sb + (c % NS) * STG;
#pragma unroll
        for (int kk = 0; kk < 4; ++kk) {
            const int cb = kk * 32 + lcb0;
            uint32_t a[4][4], bh[2][4];
#pragma unroll
            for (int mi = 0; mi < 4; ++mi)
                ldsm4(a[mi], st + SWZ((arow + mi * 16) * 128 + cb));
#pragma unroll
            for (int nj = 0; nj < 2; ++nj)
                ldsm4(bh[nj], st + 16384 + SWZ((brow + nj * 16) * 128 + cb));
#pragma unroll
            for (int mi = 0; mi < 4; ++mi)
#pragma unroll
                for (int nj = 0; nj < 2; ++nj) {
                    mma_f32(acc[mi][nj * 2 + 0], a[mi], bh[nj][0], bh[nj][2]);
                    mma_f32(acc[mi][nj * 2 + 1], a[mi], bh[nj][1], bh[nj][3]);
                }
        }
    }
}

// ---------------------------------------------------------------------------
// Q/K projections: grid.z in {0,1} selects q/k. Row-major fp16 out + bias.
// ---------------------------------------------------------------------------
__global__ void __launch_bounds__(256, 2)
gemm_proj_qk(const __half* __restrict__ A0, const __half* __restrict__ A1,
             const __half* __restrict__ B0, const __half* __restrict__ B1,
             const float* __restrict__ b0p, const float* __restrict__ b1p,
             __half* __restrict__ C0, __half* __restrict__ C1)
{
    const int bm = blockIdx.y, bn = blockIdx.x, t = blockIdx.z;
    const __half* A   = (t == 0) ? A0 : A1;
    const __half* B   = (t == 0) ? B0 : B1;
    const float* bias = (t == 0) ? b0p : b1p;
    __half* Ch        = (t == 0) ? C0 : C1;

    extern __shared__ char smem[];
    const uint32_t sb = smem_u32(smem);
    const int tid = threadIdx.x, lane = tid & 31, wid = tid >> 5;
    const int wm = wid >> 2, wn = wid & 3;

    GemmCtx cx;
    cx.gA = (const char*)(A + (size_t)(bm * 128) * MD);
    cx.gB = (const char*)(B + (size_t)(bn * 128) * MD);
    cx.ldaB = (size_t)MD * 2;
    cx.ldbB = (size_t)MD * 2;

    float acc[4][4][4];
#pragma unroll
    for (int mi = 0; mi < 4; ++mi)
#pragma unroll
        for (int nf = 0; nf < 4; ++nf)
#pragma unroll
            for (int r = 0; r < 4; ++r) acc[mi][nf][r] = 0.f;

    gemm_mainloop(cx, sb, tid, lane, wm, wn, MD / KC, acc);

    const int lr = lane >> 2;
    const int lc = (lane & 3) * 2;
#pragma unroll
    for (int mi = 0; mi < 4; ++mi) {
        const int row0 = bm * 128 + wm * 64 + mi * 16 + lr;
#pragma unroll
        for (int nf = 0; nf < 4; ++nf) {
            const int col = bn * 128 + wn * 32 + nf * 8 + lc;
            float* d = acc[mi][nf];
            const float bb0 = bias[col], bb1 = bias[col + 1];
            *(uint32_t*)(Ch + (size_t)row0 * HD + col) =
                pack_h2(__float2half_rn(d[0] + bb0), __float2half_rn(d[1] + bb1));
            *(uint32_t*)(Ch + (size_t)(row0 + 8) * HD + col) =
                pack_h2(__float2half_rn(d[2] + bb0), __float2half_rn(d[3] + bb1));
        }
    }
}

// ---------------------------------------------------------------------------
// Merged launch, grid (16, 24, 4): z = batch.
//   y < 16 -> scores tile (bm=y, bn=x, causal skip bn>bm), fp16 out * alpha
//   y >= 16 -> V projection CTA idx = z*128 + (y-16)*16 + x, writes VT.
// ---------------------------------------------------------------------------
__global__ void __launch_bounds__(256, 2)
gemm_sc_vp(const __half* __restrict__ QH, const __half* __restrict__ KH,
           __half* __restrict__ SCh, float alpha,
           const __half* __restrict__ Xv, const __half* __restrict__ Wv,
           const float* __restrict__ bv, __half* __restrict__ VT)
{
    const int z = blockIdx.z;
    extern __shared__ char smem[];
    const uint32_t sb = smem_u32(smem);
    const int tid = threadIdx.x, lane = tid & 31, wid = tid >> 5;
    const int wm = wid >> 2, wn = wid & 3;
    const int lr = lane >> 2;
    const int lc = (lane & 3) * 2;

    if (blockIdx.y < 16) {
        const int bm = blockIdx.y, bn = blockIdx.x;
        if (bn > bm) return;

        GemmCtx cx;
        cx.gA = (const char*)(QH + (size_t)z * SS * HD + (size_t)(bm * 128) * HD);
        cx.gB = (const char*)(KH + (size_t)z * SS * HD + (size_t)(bn * 128) * HD);
        cx.ldaB = (size_t)HD * 2;
        cx.ldbB = (size_t)HD * 2;

        float acc[4][4][4];
#pragma unroll
        for (int mi = 0; mi < 4; ++mi)
#pragma unroll
            for (int nf = 0; nf < 4; ++nf)
#pragma unroll
                for (int r = 0; r < 4; ++r) acc[mi][nf][r] = 0.f;

        gemm_mainloop(cx, sb, tid, lane, wm, wn, HD / KC, acc);

        __half* cp = SCh + (size_t)z * SS * SS;
#pragma unroll
        for (int mi = 0; mi < 4; ++mi) {
            const int row0 = bm * 128 + wm * 64 + mi * 16 + lr;
#pragma unroll
            for (int nf = 0; nf < 4; ++nf) {
                const int col = bn * 128 + wn * 32 + nf * 8 + lc;
                float* d = acc[mi][nf];
                *(uint32_t*)(cp + (size_t)row0 * SS + col) =
                    pack_h2(__float2half_rn(d[0] * alpha), __float2half_rn(d[1] * alpha));
                *(uint32_t*)(cp + (size_t)(row0 + 8) * SS + col) =
                    pack_h2(__float2half_rn(d[2] * alpha), __float2half_rn(d[3] * alpha));
            }
        }
    } else {
        const int idx = z * 128 + (blockIdx.y - 16) * 16 + blockIdx.x;  // 0..511
        const int bn = idx & 7;     // HD/128 = 8
        const int bm = idx >> 3;    // NT/128 = 64

        GemmCtx cx;
        cx.gA = (const char*)(Xv + (size_t)(bm * 128) * MD);
        cx.gB = (const char*)(Wv + (size_t)(bn * 128) * MD);
        cx.ldaB = (size_t)MD * 2;
        cx.ldbB = (size_t)MD * 2;

        float acc[4][4][4];
#pragma unroll
        for (int mi = 0; mi < 4; ++mi)
#pragma unroll
            for (int nf = 0; nf < 4; ++nf)
#pragma unroll
                for (int r = 0; r < 4; ++r) acc[mi][nf][r] = 0.f;

        gemm_mainloop(cx, sb, tid, lane, wm, wn, MD / KC, acc);

        // transpose tile through smem -> VT[b][h][s] coalesced
        __syncthreads();   // pipeline smem no longer in use
        constexpr int TP = 136;                 // padded row (halfs)
        __half* ts = (__half*)smem;             // [128][TP] = 34816 B
#pragma unroll
        for (int mi = 0; mi < 4; ++mi) {
            const int sl0 = wm * 64 + mi * 16 + lr;
#pragma unroll
            for (int nf = 0; nf < 4; ++nf) {
                const int hl = wn * 32 + nf * 8 + lc;
                float* d = acc[mi][nf];
                const float bb0 = bv[bn * 128 + hl], bb1 = bv[bn * 128 + hl + 1];
                ts[(hl + 0) * TP + sl0]     = __float2half_rn(d[0] + bb0);
                ts[(hl + 1) * TP + sl0]     = __float2half_rn(d[1] + bb1);
                ts[(hl + 0) * TP + sl0 + 8] = __float2half_rn(d[2] + bb0);
                ts[(hl + 1) * TP + sl0 + 8] = __float2half_rn(d[3] + bb1);
            }
        }
        __syncthreads();
        const int grow = bm * 128;
        const int b    = grow >> 11;            // SS = 2048
        const int s0   = grow & 2047;
        __half* dst = VT + (size_t)b * HD * SS + s0;
#pragma unroll
        for (int it = 0; it < 8; ++it) {        // 2048 uint4 units
            const int i2 = tid + it * 256;
            const int hl = i2 >> 4, seg = (i2 & 15) * 8;
            *(uint4*)(dst + (size_t)(bn * 128 + hl) * SS + seg) =
                *(const uint4*)&ts[hl * TP + seg];
        }
    }
}

// ---------------------------------------------------------------------------
// PV GEMM: OUT = P @ VT^T, k-chunks limited by causality, longest-first.
// ---------------------------------------------------------------------------
__global__ void __launch_bounds__(256, 2)
gemm_pv(const __half* __restrict__ A, const __half* __restrict__ B,
        float* __restrict__ Cf)
{
    const int bm = (int)gridDim.y - 1 - blockIdx.y;   // longest first
    const int bn = blockIdx.x, bz = blockIdx.z;
    const int nkt = (bm + 1) * 2;

    extern __shared__ char smem[];
    const uint32_t sb = smem_u32(smem);
    const int tid = threadIdx.x, lane = tid & 31, wid = tid >> 5;
    const int wm = wid >> 2, wn = wid & 3;

    GemmCtx cx;
    cx.gA = (const char*)(A + (size_t)bz * SS * SS + (size_t)(bm * 128) * SS);
    cx.gB = (const char*)(B + (size_t)bz * HD * SS + (size_t)(bn * 128) * SS);
    cx.ldaB = (size_t)SS * 2;
    cx.ldbB = (size_t)SS * 2;

    float acc[4][4][4];
#pragma unroll
    for (int mi = 0; mi < 4; ++mi)
#pragma unroll
        for (int nf = 0; nf < 4; ++nf)
#pragma unroll
            for (int r = 0; r < 4; ++r) acc[mi][nf][r] = 0.f;

    gemm_mainloop(cx, sb, tid, lane, wm, wn, nkt, acc);

    const int lr = lane >> 2;
    const int lc = (lane & 3) * 2;
    float* cp = Cf + (size_t)bz * SS * HD;
#pragma unroll
    for (int mi = 0; mi < 4; ++mi) {
        const int row0 = bm * 128 + wm * 64 + mi * 16 + lr;
#pragma unroll
        for (int nf = 0; nf < 4; ++nf) {
            const int col = bn * 128 + wn * 32 + nf * 8 + lc;
            float* d = acc[mi][nf];
            float2 o0 = { d[0], d[1] };
            float2 o1 = { d[2], d[3] };
            *(float2*)(cp + (size_t)row0 * HD + col) = o0;
            *(float2*)(cp + (size_t)(row0 + 8) * HD + col) = o1;
        }
    }
}

// ---------------------------------------------------------------------------
// Fused convert: grid (2048, 4). y<3 -> X tensors (2048 blocks each);
// y==3 -> the 3 W tensors packed into x<768 (256 blocks each).
// ---------------------------------------------------------------------------
__global__ void __launch_bounds__(256)
convert_hi6(const float* __restrict__ s0, const float* __restrict__ s1,
            const float* __restrict__ s2, const float* __restrict__ s3,
            const float* __restrict__ s4, const float* __restrict__ s5,
            __half* __restrict__ h0, __half* __restrict__ h1,
            __half* __restrict__ h2, __half* __restrict__ h3,
            __half* __restrict__ h4, __half* __restrict__ h5,
            size_t nX4, size_t nW4)
{
    int t;
    size_t i0;
    if (blockIdx.y < 3) {
        t = blockIdx.y;
        i0 = ((size_t)blockIdx.x * blockDim.x + threadIdx.x) * 4;
        if (i0 >= nX4) return;
    } else {
        const unsigned xb = blockIdx.x;
        if (xb >= 768) return;
        t = 3 + (int)(xb >> 8);
        i0 = ((size_t)(xb & 255) * blockDim.x + threadIdx.x) * 4;
        if (i0 >= nW4) return;
    }
    const float* src = (t == 0) ? s0 : (t == 1) ? s1 : (t == 2) ? s2
                     : (t == 3) ? s3 : (t == 4) ? s4 : s5;
    __half* hi = (t == 0) ? h0 : (t == 1) ? h1 : (t == 2) ? h2
               : (t == 3) ? h3 : (t == 4) ? h4 : h5;
    float4 x[4];
#pragma unroll
    for (int u = 0; u < 4; ++u) x[u] = ((const float4*)src)[i0 + u];
#pragma unroll
    for (int u = 0; u < 4; ++u) {
        union { __half h[4]; uint2 v; } H;
        H.h[0] = __float2half_rn(x[u].x);
        H.h[1] = __float2half_rn(x[u].y);
        H.h[2] = __float2half_rn(x[u].z);
        H.h[3] = __float2half_rn(x[u].w);
        ((uint2*)hi)[i0 + u] = H.v;
    }
}

// ---------------------------------------------------------------------------
// Masked causal softmax: SC fp16 -> P fp16, zero-filled to 128-boundary.
// ---------------------------------------------------------------------------
__global__ void __launch_bounds__(256)
softmax_rows(const int* __restrict__ mask, const __half* __restrict__ SC,
             __half* __restrict__ Phi)
{
    const int b = blockIdx.y;
    const int i = blockIdx.x;
    const size_t rowoff = ((size_t)b * SS + i) * SS;
    const __half* row = SC + rowoff;
    const int* mrow = mask + (size_t)b * SS;
    const int tid = threadIdx.x;
    const int nvalid = i + 1;
    const int nfill = ((i >> 7) + 1) << 7;
    const int j0 = tid * 8;

    float vals[8];
    float vmax = -INFINITY;
    if (j0 + 7 < nvalid) {
        uint4 r8 = *(const uint4*)(row + j0);   // 8 halfs
        const __half2* hp = (const __half2*)&r8;
        float2 f0 = __half22float2(hp[0]);
        float2 f1 = __half22float2(hp[1]);
        float2 f2 = __half22float2(hp[2]);
        float2 f3 = __half22float2(hp[3]);
        int4 m0 = *(const int4*)(mrow + j0);
        int4 m1 = *(const int4*)(mrow + j0 + 4);
        vals[0] = m0.x ? f0.x : -1e9f; vals[1] = m0.y ? f0.y : -1e9f;
        vals[2] = m0.z ? f1.x : -1e9f; vals[3] = m0.w ? f1.y : -1e9f;
        vals[4] = m1.x ? f2.x : -1e9f; vals[5] = m1.y ? f2.y : -1e9f;
        vals[6] = m1.z ? f3.x : -1e9f; vals[7] = m1.w ? f3.y : -1e9f;
#pragma unroll
        for (int t = 0; t < 8; ++t) vmax = fmaxf(vmax, vals[t]);
    } else {
#pragma unroll
        for (int t = 0; t < 8; ++t) {
            int j = j0 + t;
            float s = -INFINITY;
            if (j < nvalid) {
                s = __half2float(row[j]);
                if (mrow[j] == 0) s = -1e9f;
            }
            vals[t] = s;
            vmax = fmaxf(vmax, s);
        }
    }

    __shared__ float red[8];
#pragma unroll
    for (int o = 16; o; o >>= 1) vmax = fmaxf(vmax, __shfl_xor_sync(~0u, vmax, o));
    if ((tid & 31) == 0) red[tid >> 5] = vmax;
    __syncthreads();
    if (tid < 32) {
        float x = (tid < 8) ? red[tid] : -INFINITY;
#pragma unroll
        for (int o = 4; o; o >>= 1) x = fmaxf(x, __shfl_xor_sync(~0u, x, o));
        if (tid == 0) red[0] = x;
    }
    __syncthreads();
    vmax = red[0];
    __syncthreads();

    float lsum = 0.f;
#pragma unroll
    for (int t = 0; t < 8; ++t) {
        float e = __expf(vals[t] - vmax);
        vals[t] = e;
        lsum += e;
    }
#pragma unroll
    for (int o = 16; o; o >>= 1) lsum += __shfl_xor_sync(~0u, lsum, o);
    if ((tid & 31) == 0) red[tid >> 5] = lsum;
    __syncthreads();
    if (tid < 32) {
        float x = (tid < 8) ? red[tid] : 0.f;
#pragma unroll
        for (int o = 4; o; o >>= 1) x += __shfl_xor_sync(~0u, x, o);
        if (tid == 0) red[0] = x;
    }
    __syncthreads();
    const float rinv = 1.0f / red[0];

    if (j0 < nfill) {
        union { __half h[8]; uint4 u; } P;
#pragma unroll
        for (int t = 0; t < 8; ++t)
            P.h[t] = __float2half_rn(vals[t] * rinv);   // 0 for j > i
        *(uint4*)(Phi + rowoff + j0) = P.u;
    }
}

// ---------------------------------------------------------------------------
extern "C" void kernel_launch(void* const* d_in, const int* in_sizes, int n_in,
                              void* d_out, int out_size)
{
    (void)in_sizes; (void)n_in; (void)out_size;

    const float* q    = (const float*)d_in[0];
    const float* k    = (const float*)d_in[1];
    const float* v    = (const float*)d_in[2];
    const int*   mask = (const int*)  d_in[3];
    const float* Wq   = (const float*)d_in[4];
    const float* bq   = (const float*)d_in[5];
    const float* Wk   = (const float*)d_in[6];
    const float* bk   = (const float*)d_in[7];
    const float* Wv   = (const float*)d_in[8];
    const float* bv   = (const float*)d_in[9];
    float* out = (float*)d_out;

    static bool init = false;
    static __half *Xqh, *Xkh, *Xvh, *Wqh, *Wkh, *Wvh;
    static __half *QHh, *KHh, *VTh, *Ph, *SC;
    if (!init) {
        void* p;
        cudaGetSymbolAddress(&p, g_Xq_hi); Xqh = (__half*)p;
        cudaGetSymbolAddress(&p, g_Xk_hi); Xkh = (__half*)p;
        cudaGetSymbolAddress(&p, g_Xv_hi); Xvh = (__half*)p;
        cudaGetSymbolAddress(&p, g_Wq_hi); Wqh = (__half*)p;
        cudaGetSymbolAddress(&p, g_Wk_hi); Wkh = (__half*)p;
        cudaGetSymbolAddress(&p, g_Wv_hi); Wvh = (__half*)p;
        cudaGetSymbolAddress(&p, g_QH_hi); QHh = (__half*)p;
        cudaGetSymbolAddress(&p, g_KH_hi); KHh = (__half*)p;
        cudaGetSymbolAddress(&p, g_VT_hi); VTh = (__half*)p;
        cudaGetSymbolAddress(&p, g_P_hi);  Ph  = (__half*)p;
        cudaGetSymbolAddress(&p, g_SC);    SC  = (__half*)p;
        cudaFuncSetAttribute((const void*)gemm_proj_qk, cudaFuncAttributeMaxDynamicSharedMemorySize, SMEMSZ);
        cudaFuncSetAttribute((const void*)gemm_sc_vp,   cudaFuncAttributeMaxDynamicSharedMemorySize, SMEMSZ);
        cudaFuncSetAttribute((const void*)gemm_pv,      cudaFuncAttributeMaxDynamicSharedMemorySize, SMEMSZ);
        init = true;
    }

    // 1) Convert all 6 inputs to fp16 (tight grid: W packed into y==3)
    const size_t nX4 = (size_t)NT * MD / 4;
    const size_t nW4 = (size_t)HD * MD / 4;
    convert_hi6<<<dim3(2048, 4), 256>>>(
        q, k, v, Wq, Wk, Wv, Xqh, Xkh, Xvh, Wqh, Wkh, Wvh, nX4, nW4);

    // 2) Q/K projections in one launch
    dim3 gqk(HD / 128, NT / 128, 2);
    gemm_proj_qk<<<gqk, 256, SMEMSZ>>>(Xqh, Xkh, Wqh, Wkh, bq, bk, QHh, KHh);

    // 3) Merged: scores (y<16, causal skip) + V projection (y>=16)
    dim3 gsv(16, 24, 4);
    gemm_sc_vp<<<gsv, 256, SMEMSZ>>>(QHh, KHh, SC, 1.0f / 32.0f,
                                     Xvh, Wvh, bv, VTh);

    // 4) Softmax (fp16 scores) -> P fp16
    softmax_rows<<<dim3(SS, BB), 256>>>(mask, SC, Ph);

    // 5) OUT = P @ VT^T (longest-first CTA order)
    dim3 go(HD / 128, SS / 128, BB);
    gemm_pv<<<go, 256, SMEMSZ>>>(Ph, VTh, out);
}